// round 2
// baseline (speedup 1.0000x reference)
#include <cuda_runtime.h>
#include <cstdint>

// SSIM loss (16,3,512,512) fp32:
//   s=img1+img2, d=img1-img2  -> 4 conv fields (S, D, <s^2>, <d^2>)
//   separable 11-tap Gaussian (horizontal via shared, vertical via reg ring)
//   packed f32x2 math throughout; deterministic mean; out[0] = 1 - mean.

typedef unsigned long long u64;

#define HH 512
#define WW 512
#define BANDS 3
#define ROWS_PER_BAND 171            // 171+171+170 = 512
#define NBLOCKS 144                  // 48 planes * 3 bands (one wave on 148 SMs)
#define NTHREADS 256                 // 2 columns per thread
#define NPIX 12582912.0f

__device__ float g_partials[NBLOCKS];

// ---------- f32x2 packed helpers (sm_103a) ----------
__device__ __forceinline__ u64 pack2(float lo, float hi) {
    u64 r; asm("mov.b64 %0,{%1,%2};" : "=l"(r) : "f"(lo), "f"(hi)); return r;
}
__device__ __forceinline__ void unpack2(float& lo, float& hi, u64 v) {
    asm("mov.b64 {%0,%1},%2;" : "=f"(lo), "=f"(hi) : "l"(v));
}
__device__ __forceinline__ u64 fma2(u64 a, u64 b, u64 c) {  // a*b+c, lane-wise
    u64 d; asm("fma.rn.f32x2 %0,%1,%2,%3;" : "=l"(d) : "l"(a), "l"(b), "l"(c)); return d;
}
__device__ __forceinline__ u64 mul2(u64 a, u64 b) {
    u64 d; asm("mul.rn.f32x2 %0,%1,%2;" : "=l"(d) : "l"(a), "l"(b)); return d;
}
__device__ __forceinline__ u64 add2(u64 a, u64 b) {
    u64 d; asm("add.rn.f32x2 %0,%1,%2;" : "=l"(d) : "l"(a), "l"(b)); return d;
}
__device__ __forceinline__ u64 lds64(unsigned a) {
    u64 v; asm volatile("ld.shared.b64 %0,[%1];" : "=l"(v) : "r"(a)); return v;
}

// 1D gaussian, sigma=1.5, window 11, normalized (symmetric: KW(k)=KW(10-k)).
__device__ __forceinline__ constexpr float KW(int k) {
    constexpr float w[6] = {0.00102838f, 0.00759876f, 0.03600077f,
                            0.10936069f, 0.21300554f, 0.26601173f};
    return w[k < 6 ? k : 10 - k];
}

// Load both images' pixel pair for row rs (zero outside [0,512)).
__device__ __forceinline__ float4 ldrow(const float* __restrict__ p1,
                                        const float* __restrict__ p2, int rs) {
    if ((unsigned)rs < (unsigned)HH) {
        float2 a = *reinterpret_cast<const float2*>(p1 + (size_t)rs * WW);
        float2 b = *reinterpret_cast<const float2*>(p2 + (size_t)rs * WW);
        return make_float4(a.x, a.y, b.x, b.y);
    }
    return make_float4(0.f, 0.f, 0.f, 0.f);
}

// Shared layout: parity-split rows. Entry e = col+8 (cols -8..519, e 0..527).
// Even entries at region 0 offset e>>1, odd at region 1 offset e>>1.
// Thread t's window entries e=2t+3+m share parity per tap m -> every windowed
// LDS.64 is stride-1 across lanes: conflict-free, [reg+imm] addressing.
#define REGION_F2   264
#define REGION_B    (REGION_F2 * 8)      // 2112 bytes
#define BUF_B       (2 * REGION_B)       // 4224 bytes per buffer

__global__ void __launch_bounds__(NTHREADS, 1)
ssim_main(const float* __restrict__ img1, const float* __restrict__ img2) {
    __shared__ float2 sbuf[2][2][REGION_F2];   // [buffer][parity][offset]
    __shared__ float wsum[NTHREADS / 32];

    const int bx    = blockIdx.x;
    const int plane = bx / BANDS;
    const int band  = bx % BANDS;
    const int y0    = band * ROWS_PER_BAND;
    const int R     = min(ROWS_PER_BAND, HH - y0);

    const int t  = threadIdx.x;
    const int c0 = 2 * t;

    const float* p1 = img1 + (size_t)plane * HH * WW + c0;
    const float* p2 = img2 + (size_t)plane * HH * WW + c0;

    const unsigned sb  = (unsigned)__cvta_generic_to_shared(&sbuf[0][0][0]);
    const unsigned pE0 = sb + t * 8;                       // buf0 even region
    const unsigned pO0 = sb + REGION_B + t * 8;            // buf0 odd region
    const unsigned pE1 = pE0 + BUF_B;
    const unsigned pO1 = pO0 + BUF_B;

    // Packed weights (6 distinct, symmetric) and packed constants.
    u64 wp[6];
    #pragma unroll
    for (int k = 0; k < 6; k++) wp[k] = pack2(KW(k), KW(k));
    const u64 P025  = pack2( 0.25f,  0.25f);
    const u64 PN025 = pack2(-0.25f, -0.25f);
    const u64 P05   = pack2( 0.5f,   0.5f);
    const u64 PN05  = pack2(-0.5f,  -0.5f);
    const u64 P2    = pack2( 2.0f,   2.0f);
    const u64 PN2   = pack2(-2.0f,  -2.0f);
    const u64 PN1   = pack2(-1.0f,  -1.0f);
    const u64 C1v   = pack2(1e-4f,  1e-4f);    // 0.01^2
    const u64 C2v   = pack2(9e-4f,  9e-4f);    // 0.03^2

    // Zero the horizontal halo (cols -8..-1, 512..519) in both buffers.
    if (t < 16) {
        int e   = (t < 8) ? t : (512 + t);       // 0..7 or 520..527
        int par = e & 1, off = e >> 1;
        sbuf[0][par][off] = make_float2(0.f, 0.f);
        sbuf[1][par][off] = make_float2(0.f, 0.f);
    }

    // Vertical ring: per staged row, 4 u64: {S,D}c0 {S2,D2}c0 {S,D}c1 {S2,D2}c1
    u64 ring[11][4];

    int rs = y0 - 5;                    // next input row to stage
    float4 pre0 = ldrow(p1, p2, rs);    // 2-deep global prefetch
    float4 pre1 = ldrow(p1, p2, rs + 1);
    float sum = 0.f;

    // Unified loop: iteration u stages row y0-5+u into ring slot u%11; from
    // u>=10 it emits output row i=u-10. 11-unrolled chunks keep all ring
    // indices compile-time (registers).
    const int UMAX = R + 10;
    int u = 0;
    for (int chunk = 0; chunk < 17 && u < UMAX; chunk++) {
        #pragma unroll
        for (int j = 0; j < 11; j++) {
            if (u >= UMAX) break;
            const int buf = u & 1;

            // ---- stage row rs into shared as (s,d) per column ----
            {
                float4 cur = pre0;
                pre0 = pre1;
                pre1 = ldrow(p1, p2, rs + 2);
                rs++;
                float s0 = cur.x + cur.z, d0 = cur.x - cur.z;
                float s1 = cur.y + cur.w, d1 = cur.y - cur.w;
                sbuf[buf][0][t + 4] = make_float2(s0, d0);   // e=c0+8 (even)
                sbuf[buf][1][t + 4] = make_float2(s1, d1);   // e=c0+9 (odd)
            }
            __syncthreads();

            // ---- horizontal 11-tap conv, squares on the fly ----
            {
                const unsigned pE = buf ? pE1 : pE0;
                const unsigned pO = buf ? pO1 : pO0;
                // tap m reads region (3+m)&1 at offset t+((3+m)>>1)
                u64 vp = lds64(pO + 8 * 1);       // m=0
                u64 sp = mul2(vp, vp);
                u64 a0l = 0, a0h = 0, a1l = 0, a1h = 0;
                #pragma unroll
                for (int k = 0; k < 11; k++) {
                    const int m = k + 1;
                    const unsigned addr = (((3 + m) & 1) ? pO : pE)
                                          + 8u * ((3 + m) >> 1);
                    u64 vn = lds64(addr);
                    u64 sn = mul2(vn, vn);
                    u64 w  = wp[k < 6 ? k : 10 - k];
                    a0l = fma2(vp, w, a0l);  a0h = fma2(sp, w, a0h);
                    a1l = fma2(vn, w, a1l);  a1h = fma2(sn, w, a1h);
                    vp = vn; sp = sn;
                }
                ring[j][0] = a0l; ring[j][1] = a0h;   // slot u%11 == j
                ring[j][2] = a1l; ring[j][3] = a1h;
            }

            // ---- vertical conv + SSIM for output row i=u-10 ----
            if (u >= 10) {
                u64 v0l = 0, v0h = 0, v1l = 0, v1h = 0;
                #pragma unroll
                for (int k = 0; k < 11; k++) {
                    const int q = (j + 1 + k) % 11;   // slot of staged row i+k
                    u64 w = wp[k < 6 ? k : 10 - k];
                    v0l = fma2(ring[q][0], w, v0l);
                    v0h = fma2(ring[q][1], w, v0h);
                    v1l = fma2(ring[q][2], w, v1l);
                    v1h = fma2(ring[q][3], w, v1h);
                }
                // repack col-major -> field-major across the 2 columns
                float muS0, muD0, muS1, muD1, S20, D20, S21, D21;
                unpack2(muS0, muD0, v0l);  unpack2(S20, D20, v0h);
                unpack2(muS1, muD1, v1l);  unpack2(S21, D21, v1h);
                u64 Ps  = pack2(muS0, muS1), Pd  = pack2(muD0, muD1);
                u64 Ps2 = pack2(S20,  S21),  Pd2 = pack2(D20,  D21);

                u64 t1 = mul2(Ps, Ps);                    // mu_s^2
                u64 t2 = mul2(Pd, Pd);                    // mu_d^2
                u64 nmu12 = fma2(t2, P025, mul2(t1, PN025));   // -mu1*mu2
                u64 nmusq = fma2(t2, PN05, mul2(t1, PN05));    // -(mu1^2+mu2^2)
                u64 s12   = fma2(Ps2, P025, fma2(Pd2, PN025, nmu12));  // sigma12
                u64 ssq   = fma2(Ps2, P05,  fma2(Pd2, P05,  nmusq));   // s1^2+s2^2
                u64 num   = mul2(fma2(nmu12, PN2, C1v), fma2(s12, P2, C2v));
                u64 den   = mul2(fma2(nmusq, PN1, C1v), add2(ssq, C2v));
                float n0, n1, d0, d1;
                unpack2(n0, n1, num);
                unpack2(d0, d1, den);
                sum += __fdividef(n0, d0);
                sum += __fdividef(n1, d1);
            }
            u++;
        }
    }

    // Deterministic block reduction.
    #pragma unroll
    for (int o = 16; o > 0; o >>= 1)
        sum += __shfl_down_sync(0xFFFFFFFFu, sum, o);
    if ((t & 31) == 0) wsum[t >> 5] = sum;
    __syncthreads();
    if (t == 0) {
        float s = 0.f;
        #pragma unroll
        for (int w = 0; w < NTHREADS / 32; w++) s += wsum[w];
        g_partials[bx] = s;
    }
}

__global__ void ssim_final(float* __restrict__ out) {
    __shared__ float sh[256];
    int t = threadIdx.x;
    sh[t] = (t < NBLOCKS) ? g_partials[t] : 0.f;
    __syncthreads();
    #pragma unroll
    for (int o = 128; o > 0; o >>= 1) {
        if (t < o) sh[t] += sh[t + o];
        __syncthreads();
    }
    if (t == 0) out[0] = 1.0f - sh[0] * (1.0f / NPIX);
}

extern "C" void kernel_launch(void* const* d_in, const int* in_sizes, int n_in,
                              void* d_out, int out_size) {
    (void)in_sizes; (void)n_in; (void)out_size;
    const float* img1 = (const float*)d_in[0];
    const float* img2 = (const float*)d_in[1];
    float* out = (float*)d_out;

    ssim_main<<<NBLOCKS, NTHREADS>>>(img1, img2);
    ssim_final<<<1, 256>>>(out);
}